// round 16
// baseline (speedup 1.0000x reference)
#include <cuda_runtime.h>
#include <cuda_fp16.h>
#include <math.h>

// ---------------- problem capacity constants ----------------
#define MAXN 50000
#define MAXE 800000
#define MAXEL (MAXE + MAXN)   // edges + self loops
#define FIN 128
#define HC1MAX 256

#define PITCH_A 40   // halves; 80B rows, 16B-aligned, LDSM conflict-free
#define PITCH_B 72   // halves; 144B rows, 16B-aligned, LDSM conflict-free
#define ABYTES (128 * PITCH_A * 2)
#define BBYTES (32 * PITCH_B * 2)
#define NSTAGE 2
#define NCHUNK 3

// ---------------- device scratch (no allocations allowed) ----------------
__device__ __half g_xh[(MAXN + 128) * FIN];       // standardized x, fp16 (+pad rows)
__device__ __half g_h16a[MAXN * HC1MAX];          // layer1 GEMM output (fp16)
__device__ __half g_h16b[MAXN * HC1MAX];          // layer2 GEMM output (fp16)
__device__ __half g_out1h[(MAXN + 128) * HC1MAX]; // layer1 output (post relu), fp16 (+pad)
__device__ float  g_att[4 * MAXN * 4];            // [S1, D1, S2, D2] segments
__device__ __half g_w1h[HC1MAX * HC1MAX];         // W1 fp16
__device__ __half g_w2h[HC1MAX * HC1MAX];         // W2 fp16
__device__ int    g_counts[MAXN];
__device__ int    g_off[MAXN + 1];
__device__ int    g_cursor[MAXN];
__device__ int    g_col[MAXEL];
__device__ float  g_part[512 * 260];              // column-stat partials
__device__ float  g_mean[FIN];
__device__ float  g_istd[FIN];
__device__ int    g_is64;

static inline int ceil_div(int a, int b) { return (a + b - 1) / b; }

// ---------------- streams + events (created once, before harness runs) ------
struct SideCtx {
    cudaStream_t side;    // CSR chain
    cudaStream_t s2;      // gemm2 chunks
    cudaEvent_t  e_fork, e_join, e_g2;
    cudaEvent_t  eA[NCHUNK];
    SideCtx() {
        cudaStreamCreateWithFlags(&side, cudaStreamNonBlocking);
        cudaStreamCreateWithFlags(&s2, cudaStreamNonBlocking);
        cudaEventCreateWithFlags(&e_fork, cudaEventDisableTiming);
        cudaEventCreateWithFlags(&e_join, cudaEventDisableTiming);
        cudaEventCreateWithFlags(&e_g2, cudaEventDisableTiming);
        for (int i = 0; i < NCHUNK; i++)
            cudaEventCreateWithFlags(&eA[i], cudaEventDisableTiming);
    }
};
static SideCtx g_sc;   // static-init

__device__ __forceinline__ unsigned pack_h2(float lo, float hi) {
    __half2 h = __floats2half2_rn(lo, hi);
    return *(unsigned*)&h;
}

__device__ __forceinline__ void cp16(unsigned smem_addr, const void* gptr) {
    asm volatile("cp.async.ca.shared.global [%0], [%1], 16;"
                 :: "r"(smem_addr), "l"(gptr));
}

// ---------------- column stats (mean, std ddof=1) ----------------
__global__ void colstats1(const float* __restrict__ x, int N, int rowsPer) {
    int f = threadIdx.x;           // FIN threads
    int b = blockIdx.x;
    int r0 = b * rowsPer;
    int r1 = r0 + rowsPer; if (r1 > N) r1 = N;
    float s = 0.f, s2 = 0.f;
    for (int r = r0; r < r1; r++) {
        float v = x[(size_t)r * FIN + f];
        s += v; s2 += v * v;
    }
    g_part[b * 2 * FIN + f] = s;
    g_part[b * 2 * FIN + FIN + f] = s2;
}

__global__ void colstats2(int N, int nb) {
    __shared__ double sm_s[4][FIN], sm_s2[4][FIN];
    int f = threadIdx.x & 127;
    int g = threadIdx.x >> 7;
    double s = 0.0, s2 = 0.0;
    for (int b = g; b < nb; b += 4) {
        s  += (double)g_part[b * 2 * FIN + f];
        s2 += (double)g_part[b * 2 * FIN + FIN + f];
    }
    sm_s[g][f] = s; sm_s2[g][f] = s2;
    __syncthreads();
    if (g == 0) {
        s  = sm_s[0][f]  + sm_s[1][f]  + sm_s[2][f]  + sm_s[3][f];
        s2 = sm_s2[0][f] + sm_s2[1][f] + sm_s2[2][f] + sm_s2[3][f];
        double mean = s / (double)N;
        double var = (s2 - s * s / (double)N) / (double)(N - 1);
        g_mean[f] = (float)mean;
        g_istd[f] = (float)(1.0 / sqrt(var));
    }
}

// ---------------- fin16: standardize x -> fp16, weight cvt, att zero --------
__global__ void fin16_kernel(const float* __restrict__ x,
                             const float* __restrict__ W1,
                             const float* __restrict__ W2,
                             int N, int nW1, int nW2) {
    int idx = blockIdx.x * blockDim.x + threadIdx.x;
    int nStd = N * (FIN / 8);
    if (idx < nStd) {
        int f8 = (idx & (FIN / 8 - 1)) * 8;
        const float4* xp = (const float4*)x + (size_t)idx * 2;
        float4 v0 = xp[0], v1 = xp[1];
        float4 mn0 = *(const float4*)(g_mean + f8);
        float4 is0 = *(const float4*)(g_istd + f8);
        float4 mn1 = *(const float4*)(g_mean + f8 + 4);
        float4 is1 = *(const float4*)(g_istd + f8 + 4);
        uint4 o;
        o.x = pack_h2((v0.x - mn0.x) * is0.x, (v0.y - mn0.y) * is0.y);
        o.y = pack_h2((v0.z - mn0.z) * is0.z, (v0.w - mn0.w) * is0.w);
        o.z = pack_h2((v1.x - mn1.x) * is1.x, (v1.y - mn1.y) * is1.y);
        o.w = pack_h2((v1.z - mn1.z) * is1.z, (v1.w - mn1.w) * is1.w);
        *((uint4*)g_xh + idx) = o;
        return;
    }
    idx -= nStd;
    if (idx < 4 * MAXN) {                                 // zero att accumulators
        ((float4*)g_att)[idx] = make_float4(0.f, 0.f, 0.f, 0.f);
        return;
    }
    idx -= 4 * MAXN;
    if (idx < nW1) { g_w1h[idx] = __float2half_rn(W1[idx]); return; }
    idx -= nW1;
    if (idx < nW2) { g_w2h[idx] = __float2half_rn(W2[idx]); return; }
}

// ---------------- prep: edge-dtype detect + counts init ----------------
__global__ void prep_kernel(const unsigned int* p, int E, int N) {
    int b = blockIdx.x;
    if (b == gridDim.x - 1) {
        __shared__ unsigned int acc;
        if (threadIdx.x == 0) acc = 0u;
        __syncthreads();
        int n = E < 1024 ? E : 1024;
        unsigned int v = 0;
        for (int i = threadIdx.x; i < n; i += blockDim.x) v |= p[2 * i + 1];
        atomicOr(&acc, v);
        __syncthreads();
        if (threadIdx.x == 0) g_is64 = (acc == 0u) ? 1 : 0;
        return;
    }
    int i = b * blockDim.x + threadIdx.x;
    if (i < N) g_counts[i] = 1;   // self loop
}

__device__ __forceinline__ void get_edge(const void* ei, int E, int k, int& s, int& d) {
    if (g_is64) {
        const long long* p = (const long long*)ei;
        s = (int)p[k]; d = (int)p[E + k];
    } else {
        const int* p = (const int*)ei;
        s = p[k]; d = p[E + k];
    }
}

// ---------------- CSR build (by dst, self-loops included) ----------------
__global__ void csr_count(const void* ei, int E) {
    int k = blockIdx.x * blockDim.x + threadIdx.x;
    if (k >= E) return;
    int s, d; get_edge(ei, E, k, s, d);
    atomicAdd(&g_counts[d], 1);
}

__global__ void csr_scan(int N) {
    __shared__ int sm[1024];
    int t = threadIdx.x;
    int chunk = (N + 1023) / 1024;
    int start = t * chunk;
    int end = start + chunk; if (end > N) end = N;
    int sum = 0;
    for (int i = start; i < end; i++) sum += g_counts[i];
    sm[t] = sum;
    __syncthreads();
    for (int o = 1; o < 1024; o <<= 1) {
        int v = (t >= o) ? sm[t - o] : 0;
        __syncthreads();
        sm[t] += v;
        __syncthreads();
    }
    int run = sm[t] - sum;   // exclusive
    for (int i = start; i < end; i++) {
        g_off[i] = run;
        g_cursor[i] = run;
        run += g_counts[i];
    }
    if (t == 1023) g_off[N] = sm[1023];
}

__global__ void csr_scatter(const void* ei, int E, int N) {
    int k = blockIdx.x * blockDim.x + threadIdx.x;
    if (k >= E + N) return;
    int s, d;
    if (k < E) get_edge(ei, E, k, s, d);
    else { s = k - E; d = s; }
    int pos = atomicAdd(&g_cursor[d], 1);
    g_col[pos] = s;
}

// ---------------- fp16 tensor-core GEMM (cp.async 2-stage + ldmatrix) --------
__device__ __forceinline__ void mma_f16(float* c, const unsigned* a, const unsigned* b) {
    asm volatile(
        "mma.sync.aligned.m16n8k16.row.col.f32.f16.f16.f32 "
        "{%0,%1,%2,%3}, {%4,%5,%6,%7}, {%8,%9}, {%0,%1,%2,%3};\n"
        : "+f"(c[0]), "+f"(c[1]), "+f"(c[2]), "+f"(c[3])
        : "r"(a[0]), "r"(a[1]), "r"(a[2]), "r"(a[3]), "r"(b[0]), "r"(b[1]));
}

template <int K, int M, int C, int ASEL>
__global__ __launch_bounds__(256, 4)
void gemm_f16_kernel(const float* __restrict__ att_s,
                     const float* __restrict__ att_d, int N, int rowBase) {
    __shared__ __half As[NSTAGE][128 * PITCH_A];
    __shared__ __half Bs[NSTAGE][32 * PITCH_B];

    const int t = threadIdx.x;
    const int lane = t & 31;
    const int warp = t >> 5;
    const int groupID = lane >> 2;
    const int tig = lane & 3;
    const int warp_m = warp >> 1;   // 0..3
    const int warp_n = warp & 1;    // 0..1

    const int row0 = rowBase + blockIdx.x * 128;
    const int col0 = blockIdx.y * 64;

    const int aRow = t >> 1;          // 0..127
    const int aC0  = (t & 1) * 16;    // 0 or 16 (halves)
    const int bRow = t >> 3;          // 0..31
    const int bC0  = (t & 7) * 8;     // 0..56 (halves)

    const int gRowA = row0 + aRow;    // may exceed N; g_xh/g_out1h padded
    const int gColB = col0 + bC0;
    const bool bOK = gColB < M;

    const __half* __restrict__ Ag = ASEL ? g_out1h : g_xh;
    const __half* __restrict__ Wp = ASEL ? g_w2h : g_w1h;
    __half* __restrict__ Hout = ASEL ? g_h16b : g_h16a;

    float acc[2][4][4];
#pragma unroll
    for (int i = 0; i < 2; i++)
#pragma unroll
        for (int j = 0; j < 4; j++)
#pragma unroll
            for (int c = 0; c < 4; c++) acc[i][j][c] = 0.f;

    constexpr int T = K >> 5;

    const unsigned sA = (unsigned)__cvta_generic_to_shared(&As[0][0]);
    const unsigned sB = (unsigned)__cvta_generic_to_shared(&Bs[0][0]);
    const unsigned aDst = sA + (unsigned)((aRow * PITCH_A + aC0) * 2);
    const unsigned bDst = sB + (unsigned)((bRow * PITCH_B + bC0) * 2);

    auto stage = [&](int kb, int buf) {
        const __half* ap = Ag + (size_t)gRowA * K + kb + aC0;
        cp16(aDst + buf * ABYTES, ap);
        cp16(aDst + buf * ABYTES + 16, ap + 8);
        if (bOK) {
            const __half* bp = Wp + (size_t)(kb + bRow) * M + gColB;
            cp16(bDst + buf * BBYTES, bp);
        }
    };

    stage(0, 0);
    asm volatile("cp.async.commit_group;");

    const int mbase = warp_m * 32;
    const int nbase = warp_n * 32;

#pragma unroll
    for (int tt = 0; tt < T; tt++) {
        const int cur = tt & 1;
        if (tt + 1 < T) {
            stage((tt + 1) * 32, cur ^ 1);
            asm volatile("cp.async.commit_group;");
            asm volatile("cp.async.wait_group 1;");
        } else {
            asm volatile("cp.async.wait_group 0;");
        }
        __syncthreads();

        const unsigned aB = sA + (unsigned)(cur * ABYTES);
        const unsigned bB = sB + (unsigned)(cur * BBYTES);
#pragma unroll
        for (int k16 = 0; k16 < 32; k16 += 16) {
            unsigned a[2][4], b[2][4];
#pragma unroll
            for (int im = 0; im < 2; im++) {
                unsigned addr = aB + (unsigned)(((mbase + im * 16 + (lane & 15)) * PITCH_A
                                                + k16 + (lane >> 4) * 8) * 2);
                asm volatile("ldmatrix.sync.aligned.m8n8.x4.shared.b16 {%0,%1,%2,%3}, [%4];"
                             : "=r"(a[im][0]), "=r"(a[im][1]), "=r"(a[im][2]), "=r"(a[im][3])
                             : "r"(addr));
            }
#pragma unroll
            for (int jp = 0; jp < 2; jp++) {
                unsigned addr = bB + (unsigned)(((k16 + ((lane >> 3) & 1) * 8 + (lane & 7)) * PITCH_B
                                                + nbase + jp * 16 + (lane >> 4) * 8) * 2);
                asm volatile("ldmatrix.sync.aligned.m8n8.x4.trans.shared.b16 {%0,%1,%2,%3}, [%4];"
                             : "=r"(b[jp][0]), "=r"(b[jp][1]), "=r"(b[jp][2]), "=r"(b[jp][3])
                             : "r"(addr));
            }
#pragma unroll
            for (int im = 0; im < 2; im++)
#pragma unroll
                for (int in_ = 0; in_ < 4; in_++)
                    mma_f16(acc[im][in_], a[im], &b[in_ >> 1][(in_ & 1) * 2]);
        }
        if (tt + 1 < T) __syncthreads();
    }

    // ---- epilogue: fp16 h store ----
#pragma unroll
    for (int im = 0; im < 2; im++) {
        int r_ = row0 + warp_m * 32 + im * 16 + groupID;
#pragma unroll
        for (int in_ = 0; in_ < 4; in_++) {
            int c_ = col0 + warp_n * 32 + in_ * 8 + tig * 2;
            if (c_ < M) {
                if (r_ < N)
                    *(half2*)(Hout + (size_t)r_ * M + c_) =
                        __floats2half2_rn(acc[im][in_][0], acc[im][in_][1]);
                if (r_ + 8 < N)
                    *(half2*)(Hout + (size_t)(r_ + 8) * M + c_) =
                        __floats2half2_rn(acc[im][in_][2], acc[im][in_][3]);
            }
        }
    }

    // ---- epilogue: fused attention projections ----
    float* __restrict__ attS = g_att + (2 * ASEL) * (MAXN * 4);
    float* __restrict__ attD = g_att + (2 * ASEL + 1) * (MAXN * 4);
    const int w0 = col0 + warp_n * 32;
    if (w0 < M) {
        const int hlo = w0 / C;
        const int whi = (w0 + 31 < M - 1) ? (w0 + 31) : (M - 1);
        const int hhi = whi / C;            // warp-uniform; at most hlo+1

#pragma unroll
        for (int im = 0; im < 2; im++) {
#pragma unroll
            for (int hf = 0; hf < 2; hf++) {
                int r_ = row0 + warp_m * 32 + im * 16 + groupID + hf * 8;
                float ps0 = 0.f, ps1 = 0.f, pd0 = 0.f, pd1 = 0.f;
#pragma unroll
                for (int in_ = 0; in_ < 4; in_++) {
                    int c = w0 + in_ * 8 + tig * 2;
                    if (c < M) {
                        float a0 = acc[im][in_][hf * 2 + 0];
                        float a1 = acc[im][in_][hf * 2 + 1];
                        float sv = a0 * att_s[c] + a1 * att_s[c + 1];
                        float dv = a0 * att_d[c] + a1 * att_d[c + 1];
                        if (c / C != hlo) { ps1 += sv; pd1 += dv; }
                        else              { ps0 += sv; pd0 += dv; }
                    }
                }
                ps0 += __shfl_xor_sync(0xffffffffu, ps0, 1);
                ps0 += __shfl_xor_sync(0xffffffffu, ps0, 2);
                pd0 += __shfl_xor_sync(0xffffffffu, pd0, 1);
                pd0 += __shfl_xor_sync(0xffffffffu, pd0, 2);
                if (tig == 0 && r_ < N) {
                    atomicAdd(&attS[r_ * 4 + hlo], ps0);
                    atomicAdd(&attD[r_ * 4 + hlo], pd0);
                }
                if (hhi > hlo) {
                    ps1 += __shfl_xor_sync(0xffffffffu, ps1, 1);
                    ps1 += __shfl_xor_sync(0xffffffffu, ps1, 2);
                    pd1 += __shfl_xor_sync(0xffffffffu, pd1, 1);
                    pd1 += __shfl_xor_sync(0xffffffffu, pd1, 2);
                    if (tig == 0 && r_ < N) {
                        atomicAdd(&attS[r_ * 4 + hhi], ps1);
                        atomicAdd(&attD[r_ * 4 + hhi], pd1);
                    }
                }
            }
        }
    }
}

// ---------------- single-pass aggregation: warp per dst, [dBase,dEnd) --------
// Chunked e-prep + gather with distance-4 row prefetch.
__global__ __launch_bounds__(256)
void agg_kernel(const float* __restrict__ bias, float* __restrict__ out_ext,
                int use_ext, int dBase, int dEnd, int HC, int C,
                int do_relu, int layer) {
    __shared__ float sm_e[8][32][4];
    __shared__ int   sm_s[8][32];
    const float* __restrict__ attS = g_att + (2 * layer) * (MAXN * 4);
    const float* __restrict__ attD = g_att + (2 * layer + 1) * (MAXN * 4);
    const __half* __restrict__ hsrc = layer ? g_h16b : g_h16a;
    int w = threadIdx.x >> 5;
    int d = dBase + ((blockIdx.x * blockDim.x + threadIdx.x) >> 5);
    int lane = threadIdx.x & 31;
    if (d >= dEnd) return;
    int beg = g_off[d], end = g_off[d + 1];
    float4 ad = *(const float4*)(attD + d * 4);

    int j0 = lane * 8;                 // 8 halves per lane
    bool act = j0 < HC;                // HC=256: all lanes; HC=160: lanes 0..19
    int h0 = act ? (j0 / C) : 0;       // head for this lane's block (8 | C)
    const __half* __restrict__ hbase = hsrc + j0;

    float acc[8];
#pragma unroll
    for (int q = 0; q < 8; q++) acc[q] = 0.f;
    float den0 = 0.f, den1 = 0.f, den2 = 0.f, den3 = 0.f;

    for (int i0 = beg; i0 < end; i0 += 32) {
        int i = i0 + lane;
        bool ea = i < end;
        int s = ea ? g_col[i] : 0;
        float4 as = *(const float4*)(attS + s * 4);
        float e0 = as.x + ad.x; e0 = e0 > 0.f ? e0 : 0.2f * e0; e0 = __expf(e0);
        float e1 = as.y + ad.y; e1 = e1 > 0.f ? e1 : 0.2f * e1; e1 = __expf(e1);
        float e2 = as.z + ad.z; e2 = e2 > 0.f ? e2 : 0.2f * e2; e2 = __expf(e2);
        float e3 = as.w + ad.w; e3 = e3 > 0.f ? e3 : 0.2f * e3; e3 = __expf(e3);
        if (ea) { den0 += e0; den1 += e1; den2 += e2; den3 += e3; }
        sm_s[w][lane] = s;
        *(float4*)&sm_e[w][lane][0] = make_float4(e0, e1, e2, e3);
        __syncwarp();

        int cnt = end - i0; if (cnt > 32) cnt = 32;
        if (act) {
            // distance-4 software pipeline over the chunk (clamped prefetch idx)
            uint4 hv[4];
#pragma unroll
            for (int q = 0; q < 4; q++) {
                int jq = q < cnt ? q : cnt - 1;
                hv[q] = *(const uint4*)(hbase + (size_t)sm_s[w][jq] * HC);
            }
            for (int j = 0; j < cnt; j++) {
                int jn = j + 4 < cnt ? j + 4 : cnt - 1;
                uint4 nx = *(const uint4*)(hbase + (size_t)sm_s[w][jn] * HC);
                float aa = sm_e[w][j][h0];              // 4-way LDS, conflict-free
                float2 f0 = __half22float2(*(const half2*)&hv[0].x);
                float2 f1 = __half22float2(*(const half2*)&hv[0].y);
                float2 f2 = __half22float2(*(const half2*)&hv[0].z);
                float2 f3 = __half22float2(*(const half2*)&hv[0].w);
                acc[0] += aa * f0.x; acc[1] += aa * f0.y;
                acc[2] += aa * f1.x; acc[3] += aa * f1.y;
                acc[4] += aa * f2.x; acc[5] += aa * f2.y;
                acc[6] += aa * f3.x; acc[7] += aa * f3.y;
                hv[0] = hv[1]; hv[1] = hv[2]; hv[2] = hv[3]; hv[3] = nx;
            }
        }
        __syncwarp();
    }

#pragma unroll
    for (int o = 16; o; o >>= 1) {
        den0 += __shfl_xor_sync(0xffffffffu, den0, o);
        den1 += __shfl_xor_sync(0xffffffffu, den1, o);
        den2 += __shfl_xor_sync(0xffffffffu, den2, o);
        den3 += __shfl_xor_sync(0xffffffffu, den3, o);
    }

    if (act) {
        float dd = h0 == 0 ? den0 : (h0 == 1 ? den1 : (h0 == 2 ? den2 : den3));
        float r = 1.f / dd;
        float4 b0 = *(const float4*)(bias + j0);
        float4 b1 = *(const float4*)(bias + j0 + 4);
        float o0[4], o1[4];
        o0[0] = acc[0] * r + b0.x; o0[1] = acc[1] * r + b0.y;
        o0[2] = acc[2] * r + b0.z; o0[3] = acc[3] * r + b0.w;
        o1[0] = acc[4] * r + b1.x; o1[1] = acc[5] * r + b1.y;
        o1[2] = acc[6] * r + b1.z; o1[3] = acc[7] * r + b1.w;
        if (do_relu) {
#pragma unroll
            for (int q = 0; q < 4; q++) {
                o0[q] = fmaxf(o0[q], 0.f);
                o1[q] = fmaxf(o1[q], 0.f);
            }
        }
        if (use_ext) {
            *(float4*)(out_ext + (size_t)d * HC + j0)     = make_float4(o0[0], o0[1], o0[2], o0[3]);
            *(float4*)(out_ext + (size_t)d * HC + j0 + 4) = make_float4(o1[0], o1[1], o1[2], o1[3]);
        } else {
            uint4 pk;
            pk.x = pack_h2(o0[0], o0[1]); pk.y = pack_h2(o0[2], o0[3]);
            pk.z = pack_h2(o1[0], o1[1]); pk.w = pack_h2(o1[2], o1[3]);
            *(uint4*)(g_out1h + (size_t)d * HC + j0) = pk;
        }
    }
}

// ---------------- launch ----------------
extern "C" void kernel_launch(void* const* d_in, const int* in_sizes, int n_in,
                              void* d_out, int out_size) {
    const float* x   = (const float*)d_in[0];
    const void*  ei  = d_in[1];
    const float* W1  = (const float*)d_in[2];
    const float* as1 = (const float*)d_in[3];
    const float* ad1 = (const float*)d_in[4];
    const float* b1  = (const float*)d_in[5];
    const float* W2  = (const float*)d_in[6];
    const float* as2 = (const float*)d_in[7];
    const float* ad2 = (const float*)d_in[8];
    const float* b2  = (const float*)d_in[9];

    int E = in_sizes[1] / 2;
    int HC1 = in_sizes[5];          // 256
    int HC2 = in_sizes[9];          // 160
    int F = in_sizes[2] / HC1;      // 128
    int N = in_sizes[0] / F;        // 50000
    int C1 = HC1 / 4;               // 64
    int C2 = HC2 / 4;               // 40
    int nW1 = in_sizes[2];
    int nW2 = in_sizes[6];

    // fork point for the independent CSR chain
    cudaEventRecord(g_sc.e_fork, 0);

    // ---- main chain (legacy stream): stats -> fin16 -> gemm1 ----
    int nb = 400;
    int rowsPer = ceil_div(N, nb);
    colstats1<<<nb, FIN>>>(x, N, rowsPer);                          // launch 0
    colstats2<<<1, 512>>>(N, nb);                                   // launch 1
    {
        int work = N * (FIN / 8) + 4 * MAXN + nW1 + nW2;
        fin16_kernel<<<ceil_div(work, 256), 256>>>(x, W1, W2, N, nW1, nW2); // 2
    }
    {
        dim3 grid(ceil_div(N, 128), ceil_div(HC1, 64));
        gemm_f16_kernel<128, 256, 64, 0><<<grid, 256>>>(as1, ad1, N, 0);    // 3
    }

    // ---- side chain: edge detect + CSR build ----
    cudaStreamWaitEvent(g_sc.side, g_sc.e_fork, 0);
    prep_kernel<<<ceil_div(N, 256) + 1, 256, 0, g_sc.side>>>(
        (const unsigned int*)ei, E, N);
    csr_count<<<ceil_div(E, 256), 256, 0, g_sc.side>>>(ei, E);
    csr_scan<<<1, 1024, 0, g_sc.side>>>(N);
    csr_scatter<<<ceil_div(E + N, 256), 256, 0, g_sc.side>>>(ei, E, N);
    cudaEventRecord(g_sc.e_join, g_sc.side);

    // join: agg1 needs both gemm1 (legacy) and CSR (side)
    cudaStreamWaitEvent(0, g_sc.e_join, 0);

    // ---- chunked agg1 -> gemm2 pipeline ----
    int CH = ceil_div(ceil_div(N, NCHUNK), 128) * 128;   // 128-aligned chunk
    for (int c = 0; c < NCHUNK; c++) {
        int d0 = c * CH;
        int d1 = d0 + CH; if (d1 > N) d1 = N;
        if (d0 >= N) { cudaEventRecord(g_sc.eA[c], 0); continue; }
        agg_kernel<<<ceil_div(d1 - d0, 8), 256>>>(b1, nullptr, 0, d0, d1,
                                                  HC1, C1, 1, 0);
        cudaEventRecord(g_sc.eA[c], 0);
        // gemm2 chunk on s2, gated on this agg1 chunk
        cudaStreamWaitEvent(g_sc.s2, g_sc.eA[c], 0);
        dim3 grid(ceil_div(d1 - d0, 128), ceil_div(HC2, 64));
        gemm_f16_kernel<256, 160, 40, 1><<<grid, 256, 0, g_sc.s2>>>(as2, ad2, N, d0);
    }
    cudaEventRecord(g_sc.e_g2, g_sc.s2);
    cudaStreamWaitEvent(0, g_sc.e_g2, 0);

    // ---- layer 2 aggregation (needs full gemm2 + att2) ----
    agg_kernel<<<ceil_div(N, 8), 256>>>(b2, (float*)d_out, 1, 0, N,
                                        HC2, C2, 0, 1);
}